// round 15
// baseline (speedup 1.0000x reference)
#include <cuda_runtime.h>
#include <cuda_fp16.h>
#include <math.h>
#include <stdint.h>

#define BB 16384
#define KK 512

// ---------------- scratch (device globals; no allocations) ----------------
__device__ __half g_seq_h[BB * 512];
__device__ __half g_base_p[BB * 512];
__device__ __half g_base_f[BB * 512];
__device__ __half g_h1_p[BB * 512];
__device__ __half g_h1_f[BB * 512];
__device__ __half g_wt_p1[512 * 512];   // pw1[0:512]^T  [n][k] fp16
__device__ __half g_wt_f1[512 * 512];   // fw1[0:512]^T
__device__ __half g_wt_p2[256 * 512];   // pw2^T
__device__ __half g_wt_f2[512 * 512];   // fw2^T
__device__ __half g_wc_h[24 * 512];     // fp16 correction rows
__device__ float g_part_p[2 * BB * 2];  // [colblk 0..1][row][2]
__device__ float g_part_f[4 * BB * 2];  // [colblk 0..3][row][{pf,pe}]
__device__ float g_full_state[BB * 12]; // slot r: {act_f, act_p, act_e, 1}
__device__ float g_losses[4];

__constant__ int c_perms[6][3] = {
    {0, 1, 2}, {0, 2, 1}, {1, 0, 2}, {1, 2, 0}, {2, 0, 1}, {2, 1, 0}};

__device__ __forceinline__ float gelu_exact(float x) {
    return 0.5f * x * (1.0f + erff(x * 0.7071067811865475f));
}

// ================= PTX helpers =============================================
__device__ __forceinline__ uint32_t smem_u32(const void* p) {
    uint32_t a;
    asm("{ .reg .u64 t; cvta.to.shared.u64 t, %1; cvt.u32.u64 %0, t; }"
        : "=r"(a) : "l"(p));
    return a;
}
__device__ __forceinline__ void cp_async16(uint32_t dst, const void* src) {
    asm volatile("cp.async.ca.shared.global [%0], [%1], 16;" ::"r"(dst),
                 "l"(src) : "memory");
}
#define CP_COMMIT() asm volatile("cp.async.commit_group;" ::: "memory")
#define CP_WAIT(n) asm volatile("cp.async.wait_group %0;" ::"n"(n) : "memory")

__device__ __forceinline__ void ldsm_x4(uint32_t* r, uint32_t addr) {
    asm volatile(
        "ldmatrix.sync.aligned.m8n8.x4.shared.b16 {%0,%1,%2,%3}, [%4];"
        : "=r"(r[0]), "=r"(r[1]), "=r"(r[2]), "=r"(r[3])
        : "r"(addr));
}
__device__ __forceinline__ void mma_f16(float* c, const uint32_t* a,
                                        const uint32_t* b) {
    asm volatile(
        "mma.sync.aligned.m16n8k16.row.col.f32.f16.f16.f32 "
        "{%0,%1,%2,%3}, {%4,%5,%6,%7}, {%8,%9}, {%0,%1,%2,%3};"
        : "+f"(c[0]), "+f"(c[1]), "+f"(c[2]), "+f"(c[3])
        : "r"(a[0]), "r"(a[1]), "r"(a[2]), "r"(a[3]), "r"(b[0]), "r"(b[1]));
}

// --------- merged setup: seq convert + losses init + transposes + wc --------
__global__ void setup_kernel(const float* __restrict__ seq,
                             const float* __restrict__ pw1,
                             const float* __restrict__ fw1,
                             const float* __restrict__ pw2,
                             const float* __restrict__ fw2) {
    __shared__ float t[32][33];
    const int z = blockIdx.z;
    if (z == 0) {
        const int blk = blockIdx.y * 16 + blockIdx.x;
        const int tid = threadIdx.y * 32 + threadIdx.x;
        const int lin = blk * 256 + tid;
        for (int rep = 0; rep < 16; rep++) {
            const int base = (lin + rep * 65536) * 8;
            float4 v0 = *(const float4*)(seq + base);
            float4 v1 = *(const float4*)(seq + base + 4);
            __half2 h[4];
            h[0] = __floats2half2_rn(v0.x, v0.y);
            h[1] = __floats2half2_rn(v0.z, v0.w);
            h[2] = __floats2half2_rn(v1.x, v1.y);
            h[3] = __floats2half2_rn(v1.z, v1.w);
            *(uint4*)(g_seq_h + base) = *(uint4*)h;
        }
        if (lin < 4) g_losses[lin] = 0.f;
        return;
    }
    if (z == 5) {
        const int row = blockIdx.y * 8 + threadIdx.y;
        if (row >= 24) return;
        const int col = blockIdx.x * 32 + threadIdx.x;
        const float* src = (row < 9) ? (pw1 + (512 + row) * 512)
                                     : (fw1 + (512 + row - 9) * 512);
        g_wc_h[row * 512 + col] = __float2half_rn(src[col]);
        return;
    }
    const float* src;
    __half* dst;
    int N;
    if (z == 1) { src = pw1; dst = g_wt_p1; N = 512; }
    else if (z == 2) { src = fw1; dst = g_wt_f1; N = 512; }
    else if (z == 3) { src = pw2; dst = g_wt_p2; N = 256; }
    else { src = fw2; dst = g_wt_f2; N = 512; }
    if (blockIdx.x * 32 >= N) return;

    const int n0 = blockIdx.x * 32, k0 = blockIdx.y * 32;
#pragma unroll
    for (int i = 0; i < 4; i++)
        t[threadIdx.y + i * 8][threadIdx.x] =
            src[(k0 + threadIdx.y + i * 8) * N + n0 + threadIdx.x];
    __syncthreads();
#pragma unroll
    for (int i = 0; i < 4; i++)
        dst[(n0 + threadIdx.y + i * 8) * 512 + k0 + threadIdx.x] =
            __float2half_rn(t[threadIdx.x][threadIdx.y + i * 8]);
}

// ---------------- fp16 tensor-core GEMM, dual-problem, 4-stage pipeline -----
// BM=128, BN=128, BK=32; 256 threads (8 warps, 2x4), warp tile 64x32.
// 4 smem stages: 3 tile-loads in flight in steady state (CP_WAIT(2)).
// mode 0: store C fp16. mode 2: gelu+reduce w3 width1. mode 3: width2.
#define STG 20480
__global__ void __launch_bounds__(256, 2) gemm_dual(
    const __half* __restrict__ Ap, const __half* __restrict__ Wtp,
    const float* __restrict__ biasp, void* __restrict__ outp, int Np,
    int nbp, int modep, const float* __restrict__ w3p,
    const __half* __restrict__ Af, const __half* __restrict__ Wtf,
    const float* __restrict__ biasf, void* __restrict__ outf, int Nf,
    int modef, const float* __restrict__ w3f)
{
    extern __shared__ __align__(16) unsigned char smraw[];
    const uint32_t sb = smem_u32(smraw);

    int bx = blockIdx.x;
    const __half* A;
    const __half* Wt;
    const float* bias;
    const float* w3;
    void* outpt;
    int N, mode;
    if (bx < nbp) {
        A = Ap; Wt = Wtp; bias = biasp; outpt = outp; N = Np; mode = modep;
        w3 = w3p;
    } else {
        bx -= nbp;
        A = Af; Wt = Wtf; bias = biasf; outpt = outf; N = Nf; mode = modef;
        w3 = w3f;
    }

    const int tid = threadIdx.x;
    const int lane = tid & 31;
    const int wid = tid >> 5;
    const int warp_m = wid >> 2;
    const int warp_n = wid & 3;
    const int brow = blockIdx.y * 128;
    const int bcol = bx * 128;

    const __half* Ab = A + (size_t)brow * 512;
    const __half* Bb = Wt + (size_t)bcol * 512;

    float acc[4][4][4];
#pragma unroll
    for (int i = 0; i < 4; i++)
#pragma unroll
        for (int j = 0; j < 4; j++)
#pragma unroll
            for (int k = 0; k < 4; k++) acc[i][j][k] = 0.f;

#define LOAD_TILE(cidx, stg)                                                  \
    do {                                                                      \
        const int kc = (cidx) * 32;                                           \
        const uint32_t base = sb + (stg) * STG;                               \
        _Pragma("unroll")                                                     \
        for (int i = 0; i < 2; i++) {                                         \
            const int lin = tid + i * 256;                                    \
            const int r = lin >> 2, ch = lin & 3;                             \
            cp_async16(base + r * 80 + ch * 16,                               \
                       Ab + (size_t)r * 512 + kc + ch * 8);                   \
            cp_async16(base + 10240 + r * 80 + ch * 16,                       \
                       Bb + (size_t)r * 512 + kc + ch * 8);                   \
        }                                                                     \
    } while (0)

    LOAD_TILE(0, 0);
    CP_COMMIT();
    LOAD_TILE(1, 1);
    CP_COMMIT();
    LOAD_TILE(2, 2);
    CP_COMMIT();

    const uint32_t a_off =
        (uint32_t)(warp_m * 64 + (lane & 15)) * 80 + ((lane >> 4) << 4);
    const uint32_t b_off = 10240 +
        (uint32_t)(warp_n * 32 + ((lane >> 4) << 3) + (lane & 7)) * 80 +
        (((lane >> 3) & 1) << 4);

#pragma unroll 1
    for (int c = 0; c < 16; c++) {
        if (c <= 13) CP_WAIT(2);
        else if (c == 14) CP_WAIT(1);
        else CP_WAIT(0);
        __syncthreads();
        const uint32_t sbuf = sb + (c & 3) * STG;

#pragma unroll
        for (int ks = 0; ks < 2; ks++) {
            uint32_t a[4][4], b[4][2];
#pragma unroll
            for (int mf = 0; mf < 4; mf++)
                ldsm_x4(a[mf], sbuf + a_off + mf * (16 * 80) + ks * 32);
#pragma unroll
            for (int g = 0; g < 2; g++) {
                uint32_t r[4];
                ldsm_x4(r, sbuf + b_off + g * (16 * 80) + ks * 32);
                b[g * 2][0] = r[0]; b[g * 2][1] = r[1];
                b[g * 2 + 1][0] = r[2]; b[g * 2 + 1][1] = r[3];
            }
#pragma unroll
            for (int mf = 0; mf < 4; mf++)
#pragma unroll
                for (int nf = 0; nf < 4; nf++)
                    mma_f16(acc[mf][nf], a[mf], b[nf]);
        }

        if (c < 13) {
            LOAD_TILE(c + 3, (c + 3) & 3);
            CP_COMMIT();
        }
    }

    const int erow = warp_m * 64 + (lane >> 2);
    const int ecol = warp_n * 32 + (lane & 3) * 2;

    if (mode < 2) {
        __half* C = (__half*)outpt;
#pragma unroll
        for (int nf = 0; nf < 4; nf++) {
            const int col = bcol + ecol + nf * 8;
            const float2 bv = *(const float2*)(bias + col);
#pragma unroll
            for (int mf = 0; mf < 4; mf++) {
                float x0 = acc[mf][nf][0] + bv.x;
                float x1 = acc[mf][nf][1] + bv.y;
                float x2 = acc[mf][nf][2] + bv.x;
                float x3 = acc[mf][nf][3] + bv.y;
                if (mode == 1) {
                    x0 = gelu_exact(x0); x1 = gelu_exact(x1);
                    x2 = gelu_exact(x2); x3 = gelu_exact(x3);
                }
                const int r0 = brow + erow + mf * 16;
                *(__half2*)(C + (size_t)r0 * N + col) =
                    __floats2half2_rn(x0, x1);
                *(__half2*)(C + (size_t)(r0 + 8) * N + col) =
                    __floats2half2_rn(x2, x3);
            }
        }
    } else {
        float ps[4][2][2];
#pragma unroll
        for (int i = 0; i < 4; i++)
#pragma unroll
            for (int j = 0; j < 2; j++) { ps[i][j][0] = 0.f; ps[i][j][1] = 0.f; }

#pragma unroll
        for (int nf = 0; nf < 4; nf++) {
            const int col = bcol + ecol + nf * 8;
            const float2 bv = *(const float2*)(bias + col);
            float w3a0, w3b0, w3a1, w3b1;
            if (mode == 3) {
                const float4 w = __ldg((const float4*)(w3 + 2 * col));
                w3a0 = w.x; w3b0 = w.y; w3a1 = w.z; w3b1 = w.w;
            } else {
                const float2 w = __ldg((const float2*)(w3 + col));
                w3a0 = w.x; w3a1 = w.y; w3b0 = 0.f; w3b1 = 0.f;
            }
#pragma unroll
            for (int mf = 0; mf < 4; mf++) {
                const float x0 = gelu_exact(acc[mf][nf][0] + bv.x);
                const float x1 = gelu_exact(acc[mf][nf][1] + bv.y);
                const float x2 = gelu_exact(acc[mf][nf][2] + bv.x);
                const float x3 = gelu_exact(acc[mf][nf][3] + bv.y);
                ps[mf][0][0] += x0 * w3a0 + x1 * w3a1;
                ps[mf][0][1] += x0 * w3b0 + x1 * w3b1;
                ps[mf][1][0] += x2 * w3a0 + x3 * w3a1;
                ps[mf][1][1] += x2 * w3b0 + x3 * w3b1;
            }
        }
#pragma unroll
        for (int mf = 0; mf < 4; mf++)
#pragma unroll
            for (int pr = 0; pr < 2; pr++)
#pragma unroll
                for (int v = 0; v < 2; v++) {
                    float s = ps[mf][pr][v];
                    s += __shfl_xor_sync(0xffffffffu, s, 1);
                    s += __shfl_xor_sync(0xffffffffu, s, 2);
                    ps[mf][pr][v] = s;
                }

        float* red = (float*)smraw;
        __syncthreads();
        if ((lane & 3) == 0) {
#pragma unroll
            for (int mf = 0; mf < 4; mf++)
#pragma unroll
                for (int pr = 0; pr < 2; pr++) {
                    const int rc = warp_m * 64 + mf * 16 + pr * 8 + (lane >> 2);
                    float2 v = {ps[mf][pr][0], ps[mf][pr][1]};
                    *(float2*)&red[(warp_n * 128 + rc) * 2] = v;
                }
        }
        __syncthreads();
        if (tid < 128) {
            float2 s = {0.f, 0.f};
#pragma unroll
            for (int wn = 0; wn < 4; wn++) {
                const float2 v = *(const float2*)&red[(wn * 128 + tid) * 2];
                s.x += v.x; s.y += v.y;
            }
            float* part = (float*)outpt;
            *(float2*)&part[((size_t)bx * BB + brow + tid) * 2] = s;
        }
    }
}

// ---------------- build h1 v5: 16B weight loads, 4 rows/block ---------------
__global__ void __launch_bounds__(256) build_h1_kernel(
    const int* __restrict__ perm_idx, int step)
{
    const int tid = threadIdx.x;
    const int rh = tid >> 6;            // 0..3: row within block
    const int lt = tid & 63;
    const int b = blockIdx.x * 4 + rh;
    const int n0 = lt * 8;              // 8 cols per thread
    const int pi = __ldg(&perm_idx[b]);
    const int ridx = c_perms[pi][step];

    float a[8], f[8];

#define LD8H(dst, ptr)                                                        \
    do {                                                                      \
        const uint4 _w = __ldg((const uint4*)(ptr));                          \
        const float2 _w0 = __half22float2(*(const __half2*)&_w.x);            \
        const float2 _w1 = __half22float2(*(const __half2*)&_w.y);            \
        const float2 _w2 = __half22float2(*(const __half2*)&_w.z);            \
        const float2 _w3 = __half22float2(*(const __half2*)&_w.w);            \
        (dst)[0] = _w0.x; (dst)[1] = _w0.y; (dst)[2] = _w1.x; (dst)[3] = _w1.y;\
        (dst)[4] = _w2.x; (dst)[5] = _w2.y; (dst)[6] = _w3.x; (dst)[7] = _w3.y;\
    } while (0)

    {
        float base[8], w[8];
        LD8H(base, &g_base_p[b * 512 + n0]);
        LD8H(w, &g_wc_h[(6 + ridx) * 512 + n0]);
#pragma unroll
        for (int k = 0; k < 8; k++) a[k] = base[k] + w[k];
        LD8H(base, &g_base_f[b * 512 + n0]);
        LD8H(w, &g_wc_h[(21 + ridx) * 512 + n0]);
#pragma unroll
        for (int k = 0; k < 8; k++) f[k] = base[k] + w[k];
    }

#pragma unroll 2
    for (int t = 0; t < step; t++) {
        const int r = c_perms[pi][t];
        const float4 fv = __ldg((const float4*)&g_full_state[b * 12 + 4 * r]);
        float w[8];
        LD8H(w, &g_wc_h[(2 * r) * 512 + n0]);
#pragma unroll
        for (int k = 0; k < 8; k++) a[k] = fmaf(fv.y, w[k], a[k]);
        LD8H(w, &g_wc_h[(2 * r + 1) * 512 + n0]);
#pragma unroll
        for (int k = 0; k < 8; k++) a[k] += w[k];
        LD8H(w, &g_wc_h[(9 + 4 * r) * 512 + n0]);
#pragma unroll
        for (int k = 0; k < 8; k++) f[k] = fmaf(fv.x, w[k], f[k]);
        LD8H(w, &g_wc_h[(9 + 4 * r + 1) * 512 + n0]);
#pragma unroll
        for (int k = 0; k < 8; k++) f[k] = fmaf(fv.y, w[k], f[k]);
        LD8H(w, &g_wc_h[(9 + 4 * r + 2) * 512 + n0]);
#pragma unroll
        for (int k = 0; k < 8; k++) f[k] = fmaf(fv.z, w[k], f[k]);
        LD8H(w, &g_wc_h[(9 + 4 * r + 3) * 512 + n0]);
#pragma unroll
        for (int k = 0; k < 8; k++) f[k] += w[k];
    }

    {
        __half2 o[4];
#pragma unroll
        for (int k = 0; k < 4; k++)
            o[k] = __floats2half2_rn(gelu_exact(a[2 * k]),
                                     gelu_exact(a[2 * k + 1]));
        *(uint4*)&g_h1_p[b * 512 + n0] = *(uint4*)o;
#pragma unroll
        for (int k = 0; k < 4; k++)
            o[k] = __floats2half2_rn(gelu_exact(f[2 * k]),
                                     gelu_exact(f[2 * k + 1]));
        *(uint4*)&g_h1_f[b * 512 + n0] = *(uint4*)o;
    }
#undef LD8H
}

// ---------------- head scalar: combine partials, losses, state update -------
__global__ void __launch_bounds__(256) head_scalar_kernel(
    const float* __restrict__ pb3, const float* __restrict__ fb3,
    const float* __restrict__ freq, const float* __restrict__ pres,
    const float* __restrict__ enrich, const int* __restrict__ perm_idx,
    const int* __restrict__ round_mask, float* __restrict__ out, int step)
{
    __shared__ float blk[4];
    const int tid = threadIdx.x;
    if (tid < 4) blk[tid] = 0.f;
    __syncthreads();

    const int b = blockIdx.x * 256 + tid;

    float pp = g_part_p[(size_t)b * 2] + g_part_p[((size_t)BB + b) * 2] +
               pb3[0];
    float pf = fb3[0], pe = fb3[1];
#pragma unroll
    for (int j = 0; j < 4; j++) {
        pf += g_part_f[((size_t)j * BB + b) * 2];
        pe += g_part_f[((size_t)j * BB + b) * 2 + 1];
    }

    const int ridx = c_perms[perm_idx[b]][step];
    const float m = (float)round_mask[b * 3 + ridx];
    const float gt_f = freq[b * 3 + ridx];
    const float gt_p = pres[b * 3 + ridx];
    const float gt_e = enrich[b * 3 + ridx];

    float dlf = (pf - gt_f) * (pf - gt_f) * m;
    const float bce = fmaxf(pp, 0.f) - pp * gt_p + log1pf(expf(-fabsf(pp)));
    float dlp = bce * m;
    float dle = (pe - gt_e) * (pe - gt_e) * m;
    float dm = m;

    const bool msk = m > 0.5f;
    const float act_f = msk ? fminf(fmaxf(pf, -10.f), 10.f) : gt_f;
    const float act_p = msk ? (1.f / (1.f + expf(-pp))) : gt_p;
    const float act_e = msk ? fminf(fmaxf(pe, -100.f), 100.f) : gt_e;

    float4 fs = {act_f, act_p, act_e, 1.f};
    *(float4*)&g_full_state[b * 12 + 4 * ridx] = fs;

    out[3 + b * 3 + ridx] = act_f;
    out[3 + 3 * BB + b * 3 + ridx] = act_p;
    out[3 + 6 * BB + b * 3 + ridx] = act_e;

#pragma unroll
    for (int o = 16; o > 0; o >>= 1) {
        dlf += __shfl_xor_sync(0xffffffffu, dlf, o);
        dlp += __shfl_xor_sync(0xffffffffu, dlp, o);
        dle += __shfl_xor_sync(0xffffffffu, dle, o);
        dm  += __shfl_xor_sync(0xffffffffu, dm, o);
    }
    if ((tid & 31) == 0) {
        atomicAdd(&blk[0], dlf);
        atomicAdd(&blk[1], dlp);
        atomicAdd(&blk[2], dle);
        atomicAdd(&blk[3], dm);
    }
    __syncthreads();
    if (tid < 4) atomicAdd(&g_losses[tid], blk[tid]);
}

__global__ void finalize_kernel(float* __restrict__ out) {
    if (threadIdx.x == 0 && blockIdx.x == 0) {
        const float nm = g_losses[3] + 1e-8f;
        out[0] = g_losses[0] / nm;
        out[1] = g_losses[1] / nm;
        out[2] = g_losses[2] / nm;
    }
}

// ---------------- launcher --------------------------------------------------
extern "C" void kernel_launch(void* const* d_in, const int* in_sizes, int n_in,
                              void* d_out, int out_size)
{
    const float* seq      = (const float*)d_in[0];
    const float* freq     = (const float*)d_in[1];
    const float* pres     = (const float*)d_in[2];
    const float* enrich   = (const float*)d_in[3];
    const float* pw1      = (const float*)d_in[4];
    const float* pb1      = (const float*)d_in[5];
    const float* pw2      = (const float*)d_in[6];
    const float* pb2      = (const float*)d_in[7];
    const float* pw3      = (const float*)d_in[8];
    const float* pb3      = (const float*)d_in[9];
    const float* fw1      = (const float*)d_in[10];
    const float* fb1      = (const float*)d_in[11];
    const float* fw2      = (const float*)d_in[12];
    const float* fb2      = (const float*)d_in[13];
    const float* fw3      = (const float*)d_in[14];
    const float* fb3      = (const float*)d_in[15];
    const int*   perm_idx = (const int*)d_in[16];
    const int*   rmask    = (const int*)d_in[17];
    float* out = (float*)d_out;

    __half *seq_h, *base_p, *base_f, *h1_p, *h1_f;
    __half *wt_p1, *wt_f1, *wt_p2, *wt_f2;
    float *part_p, *part_f;
    cudaGetSymbolAddress((void**)&seq_h, g_seq_h);
    cudaGetSymbolAddress((void**)&base_p, g_base_p);
    cudaGetSymbolAddress((void**)&base_f, g_base_f);
    cudaGetSymbolAddress((void**)&h1_p, g_h1_p);
    cudaGetSymbolAddress((void**)&h1_f, g_h1_f);
    cudaGetSymbolAddress((void**)&wt_p1, g_wt_p1);
    cudaGetSymbolAddress((void**)&wt_f1, g_wt_f1);
    cudaGetSymbolAddress((void**)&wt_p2, g_wt_p2);
    cudaGetSymbolAddress((void**)&wt_f2, g_wt_f2);
    cudaGetSymbolAddress((void**)&part_p, g_part_p);
    cudaGetSymbolAddress((void**)&part_f, g_part_f);

    cudaFuncSetAttribute(gemm_dual,
                         cudaFuncAttributeMaxDynamicSharedMemorySize,
                         4 * STG);

    // merged setup: z=0 seq convert + loss init, z=1..4 transposes, z=5 wc
    setup_kernel<<<dim3(16, 16, 6), dim3(32, 8)>>>(seq, pw1, fw1, pw2, fw2);

    // step-invariant base: seq @ W1[:512] + b1 (NO gelu); both branches fused
    gemm_dual<<<dim3(8, 128), 256, 4 * STG>>>(
        seq_h, wt_p1, pb1, base_p, 512, 4, 0, nullptr,
        seq_h, wt_f1, fb1, base_f, 512, 0, nullptr);

    for (int step = 0; step < 3; step++) {
        build_h1_kernel<<<BB / 4, 256>>>(perm_idx, step);
        gemm_dual<<<dim3(6, 128), 256, 4 * STG>>>(
            h1_p, wt_p2, pb2, part_p, 256, 2, 2, pw3,
            h1_f, wt_f2, fb2, part_f, 512, 3, fw3);
        head_scalar_kernel<<<BB / 256, 256>>>(pb3, fb3, freq, pres, enrich,
                                              perm_idx, rmask, out, step);
    }

    finalize_kernel<<<1, 32>>>(out);
}

// round 16
// speedup vs baseline: 1.0197x; 1.0197x over previous
#include <cuda_runtime.h>
#include <cuda_fp16.h>
#include <math.h>
#include <stdint.h>

#define BB 16384
#define KK 512

// ---------------- scratch (device globals; no allocations) ----------------
__device__ __half g_seq_h[BB * 512];
__device__ __half g_base_p[BB * 512];
__device__ __half g_base_f[BB * 512];
__device__ __half g_h1_p[BB * 512];
__device__ __half g_h1_f[BB * 512];
__device__ __half g_wt_p1[512 * 512];   // pw1[0:512]^T  [n][k] fp16
__device__ __half g_wt_f1[512 * 512];   // fw1[0:512]^T
__device__ __half g_wt_p2[256 * 512];   // pw2^T
__device__ __half g_wt_f2[512 * 512];   // fw2^T
__device__ __half g_wc_h[24 * 512];     // fp16 correction rows
__device__ float g_part_p[2 * BB * 2];  // [colblk 0..1][row][2]
__device__ float g_part_f[4 * BB * 2];  // [colblk 0..3][row][{pf,pe}]
__device__ float g_full_state[BB * 12]; // slot r: {act_f, act_p, act_e, 1}
__device__ float g_losses[4];

__constant__ int c_perms[6][3] = {
    {0, 1, 2}, {0, 2, 1}, {1, 0, 2}, {1, 2, 0}, {2, 0, 1}, {2, 1, 0}};

__device__ __forceinline__ float gelu_exact(float x) {
    return 0.5f * x * (1.0f + erff(x * 0.7071067811865475f));
}

// ================= PTX helpers =============================================
__device__ __forceinline__ uint32_t smem_u32(const void* p) {
    uint32_t a;
    asm("{ .reg .u64 t; cvta.to.shared.u64 t, %1; cvt.u32.u64 %0, t; }"
        : "=r"(a) : "l"(p));
    return a;
}
__device__ __forceinline__ void cp_async16(uint32_t dst, const void* src) {
    asm volatile("cp.async.ca.shared.global [%0], [%1], 16;" ::"r"(dst),
                 "l"(src) : "memory");
}
#define CP_COMMIT() asm volatile("cp.async.commit_group;" ::: "memory")
#define CP_WAIT(n) asm volatile("cp.async.wait_group %0;" ::"n"(n) : "memory")

__device__ __forceinline__ void ldsm_x4(uint32_t* r, uint32_t addr) {
    asm volatile(
        "ldmatrix.sync.aligned.m8n8.x4.shared.b16 {%0,%1,%2,%3}, [%4];"
        : "=r"(r[0]), "=r"(r[1]), "=r"(r[2]), "=r"(r[3])
        : "r"(addr));
}
__device__ __forceinline__ void mma_f16(float* c, const uint32_t* a,
                                        const uint32_t* b) {
    asm volatile(
        "mma.sync.aligned.m16n8k16.row.col.f32.f16.f16.f32 "
        "{%0,%1,%2,%3}, {%4,%5,%6,%7}, {%8,%9}, {%0,%1,%2,%3};"
        : "+f"(c[0]), "+f"(c[1]), "+f"(c[2]), "+f"(c[3])
        : "r"(a[0]), "r"(a[1]), "r"(a[2]), "r"(a[3]), "r"(b[0]), "r"(b[1]));
}

// --------- merged setup: seq convert + losses init + transposes + wc --------
__global__ void setup_kernel(const float* __restrict__ seq,
                             const float* __restrict__ pw1,
                             const float* __restrict__ fw1,
                             const float* __restrict__ pw2,
                             const float* __restrict__ fw2) {
    __shared__ float t[32][33];
    const int z = blockIdx.z;
    if (z == 0) {
        const int blk = blockIdx.y * 16 + blockIdx.x;
        const int tid = threadIdx.y * 32 + threadIdx.x;
        const int lin = blk * 256 + tid;
        for (int rep = 0; rep < 16; rep++) {
            const int base = (lin + rep * 65536) * 8;
            float4 v0 = *(const float4*)(seq + base);
            float4 v1 = *(const float4*)(seq + base + 4);
            __half2 h[4];
            h[0] = __floats2half2_rn(v0.x, v0.y);
            h[1] = __floats2half2_rn(v0.z, v0.w);
            h[2] = __floats2half2_rn(v1.x, v1.y);
            h[3] = __floats2half2_rn(v1.z, v1.w);
            *(uint4*)(g_seq_h + base) = *(uint4*)h;
        }
        if (lin < 4) g_losses[lin] = 0.f;
        return;
    }
    if (z == 5) {
        const int row = blockIdx.y * 8 + threadIdx.y;
        if (row >= 24) return;
        const int col = blockIdx.x * 32 + threadIdx.x;
        const float* src = (row < 9) ? (pw1 + (512 + row) * 512)
                                     : (fw1 + (512 + row - 9) * 512);
        g_wc_h[row * 512 + col] = __float2half_rn(src[col]);
        return;
    }
    const float* src;
    __half* dst;
    int N;
    if (z == 1) { src = pw1; dst = g_wt_p1; N = 512; }
    else if (z == 2) { src = fw1; dst = g_wt_f1; N = 512; }
    else if (z == 3) { src = pw2; dst = g_wt_p2; N = 256; }
    else { src = fw2; dst = g_wt_f2; N = 512; }
    if (blockIdx.x * 32 >= N) return;

    const int n0 = blockIdx.x * 32, k0 = blockIdx.y * 32;
#pragma unroll
    for (int i = 0; i < 4; i++)
        t[threadIdx.y + i * 8][threadIdx.x] =
            src[(k0 + threadIdx.y + i * 8) * N + n0 + threadIdx.x];
    __syncthreads();
#pragma unroll
    for (int i = 0; i < 4; i++)
        dst[(n0 + threadIdx.y + i * 8) * 512 + k0 + threadIdx.x] =
            __float2half_rn(t[threadIdx.x][threadIdx.y + i * 8]);
}

// ---------------- fp16 tensor-core GEMM, dual-problem, 3-stage pipeline -----
// BM=128, BN=128, BK=32; 256 threads (8 warps, 2x4), warp tile 64x32.
// mode 0: store C fp16. mode 2: gelu+reduce w3 width1. mode 3: width2.
#define STG 20480
__global__ void __launch_bounds__(256, 2) gemm_dual(
    const __half* __restrict__ Ap, const __half* __restrict__ Wtp,
    const float* __restrict__ biasp, void* __restrict__ outp, int Np,
    int nbp, int modep, const float* __restrict__ w3p,
    const __half* __restrict__ Af, const __half* __restrict__ Wtf,
    const float* __restrict__ biasf, void* __restrict__ outf, int Nf,
    int modef, const float* __restrict__ w3f)
{
    extern __shared__ __align__(16) unsigned char smraw[];
    const uint32_t sb = smem_u32(smraw);

    int bx = blockIdx.x;
    const __half* A;
    const __half* Wt;
    const float* bias;
    const float* w3;
    void* outpt;
    int N, mode;
    if (bx < nbp) {
        A = Ap; Wt = Wtp; bias = biasp; outpt = outp; N = Np; mode = modep;
        w3 = w3p;
    } else {
        bx -= nbp;
        A = Af; Wt = Wtf; bias = biasf; outpt = outf; N = Nf; mode = modef;
        w3 = w3f;
    }

    const int tid = threadIdx.x;
    const int lane = tid & 31;
    const int wid = tid >> 5;
    const int warp_m = wid >> 2;
    const int warp_n = wid & 3;
    const int brow = blockIdx.y * 128;
    const int bcol = bx * 128;

    const __half* Ab = A + (size_t)brow * 512;
    const __half* Bb = Wt + (size_t)bcol * 512;

    float acc[4][4][4];
#pragma unroll
    for (int i = 0; i < 4; i++)
#pragma unroll
        for (int j = 0; j < 4; j++)
#pragma unroll
            for (int k = 0; k < 4; k++) acc[i][j][k] = 0.f;

#define LOAD_TILE(cidx, stg)                                                  \
    do {                                                                      \
        const int kc = (cidx) * 32;                                           \
        const uint32_t base = sb + (stg) * STG;                               \
        _Pragma("unroll")                                                     \
        for (int i = 0; i < 2; i++) {                                         \
            const int lin = tid + i * 256;                                    \
            const int r = lin >> 2, ch = lin & 3;                             \
            cp_async16(base + r * 80 + ch * 16,                               \
                       Ab + (size_t)r * 512 + kc + ch * 8);                   \
            cp_async16(base + 10240 + r * 80 + ch * 16,                       \
                       Bb + (size_t)r * 512 + kc + ch * 8);                   \
        }                                                                     \
    } while (0)

    LOAD_TILE(0, 0);
    CP_COMMIT();
    LOAD_TILE(1, 1);
    CP_COMMIT();

    const uint32_t a_off =
        (uint32_t)(warp_m * 64 + (lane & 15)) * 80 + ((lane >> 4) << 4);
    const uint32_t b_off = 10240 +
        (uint32_t)(warp_n * 32 + ((lane >> 4) << 3) + (lane & 7)) * 80 +
        (((lane >> 3) & 1) << 4);

    int stg = 0;
#pragma unroll 1
    for (int c = 0; c < 16; c++) {
        if (c < 14) CP_WAIT(1); else CP_WAIT(0);
        __syncthreads();
        const uint32_t sbuf = sb + stg * STG;

#pragma unroll
        for (int ks = 0; ks < 2; ks++) {
            uint32_t a[4][4], b[4][2];
#pragma unroll
            for (int mf = 0; mf < 4; mf++)
                ldsm_x4(a[mf], sbuf + a_off + mf * (16 * 80) + ks * 32);
#pragma unroll
            for (int g = 0; g < 2; g++) {
                uint32_t r[4];
                ldsm_x4(r, sbuf + b_off + g * (16 * 80) + ks * 32);
                b[g * 2][0] = r[0]; b[g * 2][1] = r[1];
                b[g * 2 + 1][0] = r[2]; b[g * 2 + 1][1] = r[3];
            }
#pragma unroll
            for (int mf = 0; mf < 4; mf++)
#pragma unroll
                for (int nf = 0; nf < 4; nf++)
                    mma_f16(acc[mf][nf], a[mf], b[nf]);
        }

        if (c < 14) {
            const int nstg = (stg + 2 > 2) ? stg - 1 : stg + 2;
            LOAD_TILE(c + 2, nstg);
            CP_COMMIT();
        }
        stg = (stg + 1 > 2) ? 0 : stg + 1;
    }

    const int erow = warp_m * 64 + (lane >> 2);
    const int ecol = warp_n * 32 + (lane & 3) * 2;

    if (mode < 2) {
        __half* C = (__half*)outpt;
#pragma unroll
        for (int nf = 0; nf < 4; nf++) {
            const int col = bcol + ecol + nf * 8;
            const float2 bv = *(const float2*)(bias + col);
#pragma unroll
            for (int mf = 0; mf < 4; mf++) {
                float x0 = acc[mf][nf][0] + bv.x;
                float x1 = acc[mf][nf][1] + bv.y;
                float x2 = acc[mf][nf][2] + bv.x;
                float x3 = acc[mf][nf][3] + bv.y;
                if (mode == 1) {
                    x0 = gelu_exact(x0); x1 = gelu_exact(x1);
                    x2 = gelu_exact(x2); x3 = gelu_exact(x3);
                }
                const int r0 = brow + erow + mf * 16;
                *(__half2*)(C + (size_t)r0 * N + col) =
                    __floats2half2_rn(x0, x1);
                *(__half2*)(C + (size_t)(r0 + 8) * N + col) =
                    __floats2half2_rn(x2, x3);
            }
        }
    } else {
        float ps[4][2][2];
#pragma unroll
        for (int i = 0; i < 4; i++)
#pragma unroll
            for (int j = 0; j < 2; j++) { ps[i][j][0] = 0.f; ps[i][j][1] = 0.f; }

#pragma unroll
        for (int nf = 0; nf < 4; nf++) {
            const int col = bcol + ecol + nf * 8;
            const float2 bv = *(const float2*)(bias + col);
            float w3a0, w3b0, w3a1, w3b1;
            if (mode == 3) {
                const float4 w = __ldg((const float4*)(w3 + 2 * col));
                w3a0 = w.x; w3b0 = w.y; w3a1 = w.z; w3b1 = w.w;
            } else {
                const float2 w = __ldg((const float2*)(w3 + col));
                w3a0 = w.x; w3a1 = w.y; w3b0 = 0.f; w3b1 = 0.f;
            }
#pragma unroll
            for (int mf = 0; mf < 4; mf++) {
                const float x0 = gelu_exact(acc[mf][nf][0] + bv.x);
                const float x1 = gelu_exact(acc[mf][nf][1] + bv.y);
                const float x2 = gelu_exact(acc[mf][nf][2] + bv.x);
                const float x3 = gelu_exact(acc[mf][nf][3] + bv.y);
                ps[mf][0][0] += x0 * w3a0 + x1 * w3a1;
                ps[mf][0][1] += x0 * w3b0 + x1 * w3b1;
                ps[mf][1][0] += x2 * w3a0 + x3 * w3a1;
                ps[mf][1][1] += x2 * w3b0 + x3 * w3b1;
            }
        }
#pragma unroll
        for (int mf = 0; mf < 4; mf++)
#pragma unroll
            for (int pr = 0; pr < 2; pr++)
#pragma unroll
                for (int v = 0; v < 2; v++) {
                    float s = ps[mf][pr][v];
                    s += __shfl_xor_sync(0xffffffffu, s, 1);
                    s += __shfl_xor_sync(0xffffffffu, s, 2);
                    ps[mf][pr][v] = s;
                }

        float* red = (float*)smraw;
        __syncthreads();
        if ((lane & 3) == 0) {
#pragma unroll
            for (int mf = 0; mf < 4; mf++)
#pragma unroll
                for (int pr = 0; pr < 2; pr++) {
                    const int rc = warp_m * 64 + mf * 16 + pr * 8 + (lane >> 2);
                    float2 v = {ps[mf][pr][0], ps[mf][pr][1]};
                    *(float2*)&red[(warp_n * 128 + rc) * 2] = v;
                }
        }
        __syncthreads();
        if (tid < 128) {
            float2 s = {0.f, 0.f};
#pragma unroll
            for (int wn = 0; wn < 4; wn++) {
                const float2 v = *(const float2*)&red[(wn * 128 + tid) * 2];
                s.x += v.x; s.y += v.y;
            }
            float* part = (float*)outpt;
            *(float2*)&part[((size_t)bx * BB + brow + tid) * 2] = s;
        }
    }
}

// ---------------- build h1 v5: 16B weight loads, 4 rows/block ---------------
__global__ void __launch_bounds__(256) build_h1_kernel(
    const int* __restrict__ perm_idx, int step)
{
    const int tid = threadIdx.x;
    const int rh = tid >> 6;            // 0..3: row within block
    const int lt = tid & 63;
    const int b = blockIdx.x * 4 + rh;
    const int n0 = lt * 8;              // 8 cols per thread
    const int pi = __ldg(&perm_idx[b]);
    const int ridx = c_perms[pi][step];

    float a[8], f[8];

#define LD8H(dst, ptr)                                                        \
    do {                                                                      \
        const uint4 _w = __ldg((const uint4*)(ptr));                          \
        const float2 _w0 = __half22float2(*(const __half2*)&_w.x);            \
        const float2 _w1 = __half22float2(*(const __half2*)&_w.y);            \
        const float2 _w2 = __half22float2(*(const __half2*)&_w.z);            \
        const float2 _w3 = __half22float2(*(const __half2*)&_w.w);            \
        (dst)[0] = _w0.x; (dst)[1] = _w0.y; (dst)[2] = _w1.x; (dst)[3] = _w1.y;\
        (dst)[4] = _w2.x; (dst)[5] = _w2.y; (dst)[6] = _w3.x; (dst)[7] = _w3.y;\
    } while (0)

    {
        float base[8], w[8];
        LD8H(base, &g_base_p[b * 512 + n0]);
        LD8H(w, &g_wc_h[(6 + ridx) * 512 + n0]);
#pragma unroll
        for (int k = 0; k < 8; k++) a[k] = base[k] + w[k];
        LD8H(base, &g_base_f[b * 512 + n0]);
        LD8H(w, &g_wc_h[(21 + ridx) * 512 + n0]);
#pragma unroll
        for (int k = 0; k < 8; k++) f[k] = base[k] + w[k];
    }

#pragma unroll 2
    for (int t = 0; t < step; t++) {
        const int r = c_perms[pi][t];
        const float4 fv = __ldg((const float4*)&g_full_state[b * 12 + 4 * r]);
        float w[8];
        LD8H(w, &g_wc_h[(2 * r) * 512 + n0]);
#pragma unroll
        for (int k = 0; k < 8; k++) a[k] = fmaf(fv.y, w[k], a[k]);
        LD8H(w, &g_wc_h[(2 * r + 1) * 512 + n0]);
#pragma unroll
        for (int k = 0; k < 8; k++) a[k] += w[k];
        LD8H(w, &g_wc_h[(9 + 4 * r) * 512 + n0]);
#pragma unroll
        for (int k = 0; k < 8; k++) f[k] = fmaf(fv.x, w[k], f[k]);
        LD8H(w, &g_wc_h[(9 + 4 * r + 1) * 512 + n0]);
#pragma unroll
        for (int k = 0; k < 8; k++) f[k] = fmaf(fv.y, w[k], f[k]);
        LD8H(w, &g_wc_h[(9 + 4 * r + 2) * 512 + n0]);
#pragma unroll
        for (int k = 0; k < 8; k++) f[k] = fmaf(fv.z, w[k], f[k]);
        LD8H(w, &g_wc_h[(9 + 4 * r + 3) * 512 + n0]);
#pragma unroll
        for (int k = 0; k < 8; k++) f[k] += w[k];
    }

    {
        __half2 o[4];
#pragma unroll
        for (int k = 0; k < 4; k++)
            o[k] = __floats2half2_rn(gelu_exact(a[2 * k]),
                                     gelu_exact(a[2 * k + 1]));
        *(uint4*)&g_h1_p[b * 512 + n0] = *(uint4*)o;
#pragma unroll
        for (int k = 0; k < 4; k++)
            o[k] = __floats2half2_rn(gelu_exact(f[2 * k]),
                                     gelu_exact(f[2 * k + 1]));
        *(uint4*)&g_h1_f[b * 512 + n0] = *(uint4*)o;
    }
#undef LD8H
}

// ---------------- head scalar: combine partials, losses, state update -------
__global__ void __launch_bounds__(256) head_scalar_kernel(
    const float* __restrict__ pb3, const float* __restrict__ fb3,
    const float* __restrict__ freq, const float* __restrict__ pres,
    const float* __restrict__ enrich, const int* __restrict__ perm_idx,
    const int* __restrict__ round_mask, float* __restrict__ out, int step)
{
    __shared__ float blk[4];
    const int tid = threadIdx.x;
    if (tid < 4) blk[tid] = 0.f;
    __syncthreads();

    const int b = blockIdx.x * 256 + tid;

    float pp = g_part_p[(size_t)b * 2] + g_part_p[((size_t)BB + b) * 2] +
               pb3[0];
    float pf = fb3[0], pe = fb3[1];
#pragma unroll
    for (int j = 0; j < 4; j++) {
        pf += g_part_f[((size_t)j * BB + b) * 2];
        pe += g_part_f[((size_t)j * BB + b) * 2 + 1];
    }

    const int ridx = c_perms[perm_idx[b]][step];
    const float m = (float)round_mask[b * 3 + ridx];
    const float gt_f = freq[b * 3 + ridx];
    const float gt_p = pres[b * 3 + ridx];
    const float gt_e = enrich[b * 3 + ridx];

    float dlf = (pf - gt_f) * (pf - gt_f) * m;
    const float bce = fmaxf(pp, 0.f) - pp * gt_p + log1pf(expf(-fabsf(pp)));
    float dlp = bce * m;
    float dle = (pe - gt_e) * (pe - gt_e) * m;
    float dm = m;

    const bool msk = m > 0.5f;
    const float act_f = msk ? fminf(fmaxf(pf, -10.f), 10.f) : gt_f;
    const float act_p = msk ? (1.f / (1.f + expf(-pp))) : gt_p;
    const float act_e = msk ? fminf(fmaxf(pe, -100.f), 100.f) : gt_e;

    float4 fs = {act_f, act_p, act_e, 1.f};
    *(float4*)&g_full_state[b * 12 + 4 * ridx] = fs;

    out[3 + b * 3 + ridx] = act_f;
    out[3 + 3 * BB + b * 3 + ridx] = act_p;
    out[3 + 6 * BB + b * 3 + ridx] = act_e;

#pragma unroll
    for (int o = 16; o > 0; o >>= 1) {
        dlf += __shfl_xor_sync(0xffffffffu, dlf, o);
        dlp += __shfl_xor_sync(0xffffffffu, dlp, o);
        dle += __shfl_xor_sync(0xffffffffu, dle, o);
        dm  += __shfl_xor_sync(0xffffffffu, dm, o);
    }
    if ((tid & 31) == 0) {
        atomicAdd(&blk[0], dlf);
        atomicAdd(&blk[1], dlp);
        atomicAdd(&blk[2], dle);
        atomicAdd(&blk[3], dm);
    }
    __syncthreads();
    if (tid < 4) atomicAdd(&g_losses[tid], blk[tid]);
}

__global__ void finalize_kernel(float* __restrict__ out) {
    if (threadIdx.x == 0 && blockIdx.x == 0) {
        const float nm = g_losses[3] + 1e-8f;
        out[0] = g_losses[0] / nm;
        out[1] = g_losses[1] / nm;
        out[2] = g_losses[2] / nm;
    }
}

// ---------------- launcher --------------------------------------------------
extern "C" void kernel_launch(void* const* d_in, const int* in_sizes, int n_in,
                              void* d_out, int out_size)
{
    const float* seq      = (const float*)d_in[0];
    const float* freq     = (const float*)d_in[1];
    const float* pres     = (const float*)d_in[2];
    const float* enrich   = (const float*)d_in[3];
    const float* pw1      = (const float*)d_in[4];
    const float* pb1      = (const float*)d_in[5];
    const float* pw2      = (const float*)d_in[6];
    const float* pb2      = (const float*)d_in[7];
    const float* pw3      = (const float*)d_in[8];
    const float* pb3      = (const float*)d_in[9];
    const float* fw1      = (const float*)d_in[10];
    const float* fb1      = (const float*)d_in[11];
    const float* fw2      = (const float*)d_in[12];
    const float* fb2      = (const float*)d_in[13];
    const float* fw3      = (const float*)d_in[14];
    const float* fb3      = (const float*)d_in[15];
    const int*   perm_idx = (const int*)d_in[16];
    const int*   rmask    = (const int*)d_in[17];
    float* out = (float*)d_out;

    __half *seq_h, *base_p, *base_f, *h1_p, *h1_f;
    __half *wt_p1, *wt_f1, *wt_p2, *wt_f2;
    float *part_p, *part_f;
    cudaGetSymbolAddress((void**)&seq_h, g_seq_h);
    cudaGetSymbolAddress((void**)&base_p, g_base_p);
    cudaGetSymbolAddress((void**)&base_f, g_base_f);
    cudaGetSymbolAddress((void**)&h1_p, g_h1_p);
    cudaGetSymbolAddress((void**)&h1_f, g_h1_f);
    cudaGetSymbolAddress((void**)&wt_p1, g_wt_p1);
    cudaGetSymbolAddress((void**)&wt_f1, g_wt_f1);
    cudaGetSymbolAddress((void**)&wt_p2, g_wt_p2);
    cudaGetSymbolAddress((void**)&wt_f2, g_wt_f2);
    cudaGetSymbolAddress((void**)&part_p, g_part_p);
    cudaGetSymbolAddress((void**)&part_f, g_part_f);

    cudaFuncSetAttribute(gemm_dual,
                         cudaFuncAttributeMaxDynamicSharedMemorySize,
                         3 * STG);

    // merged setup: z=0 seq convert + loss init, z=1..4 transposes, z=5 wc
    setup_kernel<<<dim3(16, 16, 6), dim3(32, 8)>>>(seq, pw1, fw1, pw2, fw2);

    // step-invariant base: seq @ W1[:512] + b1 (NO gelu); both branches fused
    gemm_dual<<<dim3(8, 128), 256, 3 * STG>>>(
        seq_h, wt_p1, pb1, base_p, 512, 4, 0, nullptr,
        seq_h, wt_f1, fb1, base_f, 512, 0, nullptr);

    for (int step = 0; step < 3; step++) {
        build_h1_kernel<<<BB / 4, 256>>>(perm_idx, step);
        gemm_dual<<<dim3(6, 128), 256, 3 * STG>>>(
            h1_p, wt_p2, pb2, part_p, 256, 2, 2, pw3,
            h1_f, wt_f2, fb2, part_f, 512, 3, fw3);
        head_scalar_kernel<<<BB / 256, 256>>>(pb3, fb3, freq, pres, enrich,
                                              perm_idx, rmask, out, step);
    }

    finalize_kernel<<<1, 32>>>(out);
}